// round 12
// baseline (speedup 1.0000x reference)
#include <cuda_runtime.h>
#include <cuda_fp16.h>
#include <mma.h>
#include <math.h>

using namespace nvcuda;

#define NN 100000
#define EE 1600000
#define FD 128
#define HD 64

// Scratch (device globals)
__device__ int    g_cnt[2 * NN + 32];       // [0..NN)=out, [NN..2NN)=in, [2NN]=scan ticket
__device__ float  g_nsrc[NN];
__device__ float  g_ndst[NN];
__device__ int    g_off[NN];
__device__ int    g_cursor[NN];
__device__ int    g_csr[EE];
__device__ __half g_x16[(size_t)NN * HD];   // x = (feat*nsrc)@W1 (fp16)
__device__ __half g_y16[(size_t)NN * HD];   // y = relu(agg1*ndst+b1)*nsrc (fp16)
__device__ __half g_a16[(size_t)NN * HD];   // agg2*ndst (fp16, wmma A input)

// ---------------------------------------------------------------------------
// Degrees (R4-proven: 4 edges/thread)
// ---------------------------------------------------------------------------
__global__ void deg_kernel(const int* __restrict__ src, const int* __restrict__ dst, int E) {
    int i = (blockIdx.x * blockDim.x + threadIdx.x) * 4;
    if (i + 4 <= E) {
        int4 s = *(const int4*)(src + i);
        int4 d = *(const int4*)(dst + i);
        atomicAdd(&g_cnt[s.x], 1); atomicAdd(&g_cnt[s.y], 1);
        atomicAdd(&g_cnt[s.z], 1); atomicAdd(&g_cnt[s.w], 1);
        atomicAdd(&g_cnt[NN + d.x], 1); atomicAdd(&g_cnt[NN + d.y], 1);
        atomicAdd(&g_cnt[NN + d.z], 1); atomicAdd(&g_cnt[NN + d.w], 1);
    } else {
        for (int j = i; j < E; j++) {
            atomicAdd(&g_cnt[src[j]], 1);
            atomicAdd(&g_cnt[NN + dst[j]], 1);
        }
    }
}

// ---------------------------------------------------------------------------
// Scan + norm fused (R4-proven)
// ---------------------------------------------------------------------------
__global__ void __launch_bounds__(256) scan_norm_kernel(int N) {
    __shared__ int wsum[8];
    __shared__ int sbase;
    int i = blockIdx.x * 256 + threadIdx.x;
    int lane = threadIdx.x & 31, wid = threadIdx.x >> 5;

    int cin = (i < N) ? g_cnt[NN + i] : 0;
    int x = cin;
#pragma unroll
    for (int o = 1; o < 32; o <<= 1) {
        int n = __shfl_up_sync(0xffffffffu, x, o);
        if (lane >= o) x += n;
    }
    if (lane == 31) wsum[wid] = x;
    __syncthreads();
    if (threadIdx.x == 0) {
        int run = 0;
#pragma unroll
        for (int w = 0; w < 8; w++) { run += wsum[w]; wsum[w] = run; }
        sbase = atomicAdd(&g_cnt[2 * NN], run);
    }
    __syncthreads();
    int excl = x - cin + (wid > 0 ? wsum[wid - 1] : 0) + sbase;
    if (i < N) {
        g_off[i] = excl;
        g_cursor[i] = excl;
        g_nsrc[i] = rsqrtf(fmaxf((float)g_cnt[i], 1.0f));
        g_ndst[i] = rsqrtf(fmaxf((float)cin, 1.0f));
    }
}

// ---------------------------------------------------------------------------
// Fill CSR: 1 edge per thread (R4-proven)
// ---------------------------------------------------------------------------
__global__ void fill_kernel(const int* __restrict__ src, const int* __restrict__ dst, int E) {
    int i = blockIdx.x * blockDim.x + threadIdx.x;
    if (i < E) {
        int p = atomicAdd(&g_cursor[dst[i]], 1);
        g_csr[p] = src[i];
    }
}

// ---------------------------------------------------------------------------
// GEMM1 (wmma HMMA, R9-proven): x16 = fp16( (feat * nsrc) @ W1 )
// ---------------------------------------------------------------------------
__global__ void __launch_bounds__(256) gemm1_kernel(const float* __restrict__ feat,
                                                    const float* __restrict__ W1, int N) {
    __shared__ __align__(32) __half As[64][136];
    __shared__ __align__(32) __half Bs[128][72];
    int tid = threadIdx.x;
    int w = tid >> 5;
    int r0 = blockIdx.x * 64;

    for (int idx = tid; idx < 2048; idx += 256) {
        int r = idx >> 5;
        int c4 = idx & 31;
        int row = r0 + r;
        float4 v = make_float4(0.f, 0.f, 0.f, 0.f);
        float s = 0.f;
        if (row < N) {
            v = ((const float4*)(feat + (size_t)row * FD))[c4];
            s = g_nsrc[row];
        }
        __half2 h0 = __floats2half2_rn(v.x * s, v.y * s);
        __half2 h1 = __floats2half2_rn(v.z * s, v.w * s);
        uint2 pk; pk.x = *(unsigned*)&h0; pk.y = *(unsigned*)&h1;
        *(uint2*)&As[r][c4 * 4] = pk;
    }
    for (int idx = tid; idx < 2048; idx += 256) {
        int k = idx >> 4;
        int c4 = idx & 15;
        float4 v = ((const float4*)(W1 + (size_t)k * HD))[c4];
        __half2 h0 = __floats2half2_rn(v.x, v.y);
        __half2 h1 = __floats2half2_rn(v.z, v.w);
        uint2 pk; pk.x = *(unsigned*)&h0; pk.y = *(unsigned*)&h1;
        *(uint2*)&Bs[k][c4 * 4] = pk;
    }
    __syncthreads();

    int rg = w >> 1;
    int cg = (w & 1) * 2;
    wmma::fragment<wmma::accumulator, 16, 16, 16, float> c0, c1;
    wmma::fill_fragment(c0, 0.0f);
    wmma::fill_fragment(c1, 0.0f);
#pragma unroll
    for (int k = 0; k < 8; k++) {
        wmma::fragment<wmma::matrix_a, 16, 16, 16, __half, wmma::row_major> a;
        wmma::fragment<wmma::matrix_b, 16, 16, 16, __half, wmma::row_major> b0, b1;
        wmma::load_matrix_sync(a, &As[rg * 16][k * 16], 136);
        wmma::load_matrix_sync(b0, &Bs[k * 16][cg * 16], 72);
        wmma::load_matrix_sync(b1, &Bs[k * 16][(cg + 1) * 16], 72);
        wmma::mma_sync(c0, a, b0, c0);
        wmma::mma_sync(c1, a, b1, c1);
    }
    __syncthreads();

    float* Cs = (float*)&As[0][0];
    wmma::store_matrix_sync(Cs + (rg * 16) * 68 + cg * 16, c0, 68, wmma::mem_row_major);
    wmma::store_matrix_sync(Cs + (rg * 16) * 68 + (cg + 1) * 16, c1, 68, wmma::mem_row_major);
    __syncthreads();

    for (int idx = tid; idx < 1024; idx += 256) {
        int r = idx >> 4;
        int c4 = idx & 15;
        int row = r0 + r;
        if (row < N) {
            const float* p = Cs + r * 68 + c4 * 4;
            __half2 h0 = __floats2half2_rn(p[0], p[1]);
            __half2 h1 = __floats2half2_rn(p[2], p[3]);
            uint2 pk; pk.x = *(unsigned*)&h0; pk.y = *(unsigned*)&h1;
            *(uint2*)(g_x16 + (size_t)row * HD + c4 * 4) = pk;
        }
    }
}

// ---------------------------------------------------------------------------
// Shuffle-batched gather core, 8-wide batches (MLP=8 vs prior 4)
// ---------------------------------------------------------------------------
__device__ __forceinline__ void gather8(const __half* __restrict__ X, int lane,
                                        int r0, int r1, int r2, int r3,
                                        int r4, int r5, int r6, int r7,
                                        float& ax, float& ay) {
    float2 v0 = __half22float2(*(const __half2*)(X + (size_t)r0 * HD + lane * 2));
    float2 v1 = __half22float2(*(const __half2*)(X + (size_t)r1 * HD + lane * 2));
    float2 v2 = __half22float2(*(const __half2*)(X + (size_t)r2 * HD + lane * 2));
    float2 v3 = __half22float2(*(const __half2*)(X + (size_t)r3 * HD + lane * 2));
    float2 v4 = __half22float2(*(const __half2*)(X + (size_t)r4 * HD + lane * 2));
    float2 v5 = __half22float2(*(const __half2*)(X + (size_t)r5 * HD + lane * 2));
    float2 v6 = __half22float2(*(const __half2*)(X + (size_t)r6 * HD + lane * 2));
    float2 v7 = __half22float2(*(const __half2*)(X + (size_t)r7 * HD + lane * 2));
    ax += ((v0.x + v1.x) + (v2.x + v3.x)) + ((v4.x + v5.x) + (v6.x + v7.x));
    ay += ((v0.y + v1.y) + (v2.y + v3.y)) + ((v4.y + v5.y) + (v6.y + v7.y));
}

__device__ __forceinline__ void gather_row(const __half* __restrict__ X,
                                           int beg, int end, int lane,
                                           float& ax, float& ay) {
    ax = 0.f; ay = 0.f;
    int j = beg;
    for (; j + 32 <= end; j += 32) {
        int s = g_csr[j + lane];
#pragma unroll
        for (int t = 0; t < 32; t += 8) {
            int r0 = __shfl_sync(0xffffffffu, s, t + 0);
            int r1 = __shfl_sync(0xffffffffu, s, t + 1);
            int r2 = __shfl_sync(0xffffffffu, s, t + 2);
            int r3 = __shfl_sync(0xffffffffu, s, t + 3);
            int r4 = __shfl_sync(0xffffffffu, s, t + 4);
            int r5 = __shfl_sync(0xffffffffu, s, t + 5);
            int r6 = __shfl_sync(0xffffffffu, s, t + 6);
            int r7 = __shfl_sync(0xffffffffu, s, t + 7);
            gather8(X, lane, r0, r1, r2, r3, r4, r5, r6, r7, ax, ay);
        }
    }
    int rem = end - j;
    if (rem > 0) {
        int s = (lane < rem) ? g_csr[j + lane] : 0;
        int t = 0;
        for (; t + 8 <= rem; t += 8) {
            int r0 = __shfl_sync(0xffffffffu, s, t + 0);
            int r1 = __shfl_sync(0xffffffffu, s, t + 1);
            int r2 = __shfl_sync(0xffffffffu, s, t + 2);
            int r3 = __shfl_sync(0xffffffffu, s, t + 3);
            int r4 = __shfl_sync(0xffffffffu, s, t + 4);
            int r5 = __shfl_sync(0xffffffffu, s, t + 5);
            int r6 = __shfl_sync(0xffffffffu, s, t + 6);
            int r7 = __shfl_sync(0xffffffffu, s, t + 7);
            gather8(X, lane, r0, r1, r2, r3, r4, r5, r6, r7, ax, ay);
        }
        for (; t + 4 <= rem; t += 4) {
            int r0 = __shfl_sync(0xffffffffu, s, t + 0);
            int r1 = __shfl_sync(0xffffffffu, s, t + 1);
            int r2 = __shfl_sync(0xffffffffu, s, t + 2);
            int r3 = __shfl_sync(0xffffffffu, s, t + 3);
            float2 v0 = __half22float2(*(const __half2*)(X + (size_t)r0 * HD + lane * 2));
            float2 v1 = __half22float2(*(const __half2*)(X + (size_t)r1 * HD + lane * 2));
            float2 v2 = __half22float2(*(const __half2*)(X + (size_t)r2 * HD + lane * 2));
            float2 v3 = __half22float2(*(const __half2*)(X + (size_t)r3 * HD + lane * 2));
            ax += (v0.x + v1.x) + (v2.x + v3.x);
            ay += (v0.y + v1.y) + (v2.y + v3.y);
        }
        for (; t < rem; t++) {
            int r = __shfl_sync(0xffffffffu, s, t);
            float2 v = __half22float2(*(const __half2*)(X + (size_t)r * HD + lane * 2));
            ax += v.x; ay += v.y;
        }
    }
}

__global__ void __launch_bounds__(256) gather1_kernel(const float* __restrict__ b1, int N) {
    int warp = (blockIdx.x * blockDim.x + threadIdx.x) >> 5;
    int lane = threadIdx.x & 31;
    if (warp >= N) return;
    int beg = g_off[warp];
    int end = beg + g_cnt[NN + warp];

    float ax, ay;
    gather_row(g_x16, beg, end, lane, ax, ay);

    float nd = g_ndst[warp];
    float ns = g_nsrc[warp];
    float2 b = *(const float2*)(b1 + lane * 2);
    float ox = fmaxf(ax * nd + b.x, 0.f) * ns;
    float oy = fmaxf(ay * nd + b.y, 0.f) * ns;
    *(__half2*)(g_y16 + (size_t)warp * HD + lane * 2) = __floats2half2_rn(ox, oy);
}

__global__ void __launch_bounds__(256) gather2_kernel(int N) {
    int warp = (blockIdx.x * blockDim.x + threadIdx.x) >> 5;
    int lane = threadIdx.x & 31;
    if (warp >= N) return;
    int beg = g_off[warp];
    int end = beg + g_cnt[NN + warp];

    float ax, ay;
    gather_row(g_y16, beg, end, lane, ax, ay);

    float nd = g_ndst[warp];
    *(__half2*)(g_a16 + (size_t)warp * HD + lane * 2) = __floats2half2_rn(ax * nd, ay * nd);
}

// ---------------------------------------------------------------------------
// Final (wmma HMMA dual-GEMM, R9-proven) with __expf epilogue
// ---------------------------------------------------------------------------
__global__ void __launch_bounds__(256) final_kernel(const float* __restrict__ noise,
                                                    const float* __restrict__ W_mu,
                                                    const float* __restrict__ b_mu,
                                                    const float* __restrict__ W_sig,
                                                    const float* __restrict__ b_sig,
                                                    float* __restrict__ out, int N) {
    __shared__ __align__(32) char sbuf[64 * 132 * 4];    // 33792 B union
    __half* As = (__half*)sbuf;                          // [64][72]  = 9216 B
    __half* Bs = (__half*)(sbuf + 9216);                 // [64][136] = 17408 B
    float*  Cs = (float*)sbuf;                           // [64][132] (after mma)
    int tid = threadIdx.x;
    int w = tid >> 5;
    int r0 = blockIdx.x * 64;

    for (int idx = tid; idx < 1024; idx += 256) {
        int r = idx >> 4;
        int c4 = idx & 15;
        int row = r0 + r;
        uint2 pk = make_uint2(0u, 0u);
        if (row < N) pk = *(const uint2*)(g_a16 + (size_t)row * HD + c4 * 4);
        *(uint2*)&As[r * 72 + c4 * 4] = pk;
    }
    for (int idx = tid; idx < 2048; idx += 256) {
        int k = idx >> 5;
        int c4 = idx & 31;
        float4 v = (c4 < 16) ? ((const float4*)(W_mu + (size_t)k * HD))[c4]
                             : ((const float4*)(W_sig + (size_t)k * HD))[c4 - 16];
        __half2 h0 = __floats2half2_rn(v.x, v.y);
        __half2 h1 = __floats2half2_rn(v.z, v.w);
        uint2 pk; pk.x = *(unsigned*)&h0; pk.y = *(unsigned*)&h1;
        *(uint2*)&Bs[k * 136 + c4 * 4] = pk;
    }
    __syncthreads();

    int rg = w >> 1;
    int ch = (w & 1) * 4;
    wmma::fragment<wmma::accumulator, 16, 16, 16, float> c[4];
#pragma unroll
    for (int f = 0; f < 4; f++) wmma::fill_fragment(c[f], 0.0f);
#pragma unroll
    for (int k = 0; k < 4; k++) {
        wmma::fragment<wmma::matrix_a, 16, 16, 16, __half, wmma::row_major> a;
        wmma::load_matrix_sync(a, &As[rg * 16 * 72 + k * 16], 72);
#pragma unroll
        for (int f = 0; f < 4; f++) {
            wmma::fragment<wmma::matrix_b, 16, 16, 16, __half, wmma::row_major> b;
            wmma::load_matrix_sync(b, &Bs[k * 16 * 136 + (ch + f) * 16], 136);
            wmma::mma_sync(c[f], a, b, c[f]);
        }
    }
    __syncthreads();
#pragma unroll
    for (int f = 0; f < 4; f++)
        wmma::store_matrix_sync(Cs + (rg * 16) * 132 + (ch + f) * 16, c[f], 132,
                                wmma::mem_row_major);
    __syncthreads();

    int tx = tid & 15, ty = tid >> 4;
    float4 bm = *(const float4*)(b_mu + tx * 4);
    float4 bsg = *(const float4*)(b_sig + tx * 4);
#pragma unroll
    for (int i = 0; i < 4; i++) {
        int r = ty * 4 + i;
        int row = r0 + r;
        if (row < N) {
            const float* pm = Cs + r * 132 + tx * 4;
            const float* ps = Cs + r * 132 + 64 + tx * 4;
            float4 nz = *(const float4*)(noise + (size_t)row * HD + tx * 4);
            float4 o;
            o.x = (pm[0] + bm.x) + nz.x * __expf(ps[0] + bsg.x);
            o.y = (pm[1] + bm.y) + nz.y * __expf(ps[1] + bsg.y);
            o.z = (pm[2] + bm.z) + nz.z * __expf(ps[2] + bsg.z);
            o.w = (pm[3] + bm.w) + nz.w * __expf(ps[3] + bsg.w);
            *(float4*)(out + (size_t)row * HD + tx * 4) = o;
        }
    }
}

// ---------------------------------------------------------------------------
// Launch — exact R9 structure
// ---------------------------------------------------------------------------
static cudaStream_t s2 = nullptr;
static cudaEvent_t  evScan = nullptr, evGemm = nullptr;

extern "C" void kernel_launch(void* const* d_in, const int* in_sizes, int n_in,
                              void* d_out, int out_size) {
    const float* feat  = (const float*)d_in[0];
    const int*   src   = (const int*)d_in[1];
    const int*   dst   = (const int*)d_in[2];
    const float* noise = (const float*)d_in[3];
    const float* W1    = (const float*)d_in[4];
    const float* b1    = (const float*)d_in[5];
    const float* W_mu  = (const float*)d_in[6];
    const float* b_mu  = (const float*)d_in[7];
    const float* W_sig = (const float*)d_in[8];
    const float* b_sig = (const float*)d_in[9];

    int N = in_sizes[0] / FD;
    int E = in_sizes[1];

    if (s2 == nullptr) {
        cudaStreamCreateWithFlags(&s2, cudaStreamNonBlocking);
        cudaEventCreateWithFlags(&evScan, cudaEventDisableTiming);
        cudaEventCreateWithFlags(&evGemm, cudaEventDisableTiming);
    }

    void* p_cnt;
    cudaGetSymbolAddress(&p_cnt, g_cnt);
    cudaMemsetAsync(p_cnt, 0, sizeof(int) * (2 * NN + 32));

    deg_kernel<<<(E / 4 + 255) / 256, 256>>>(src, dst, E);
    scan_norm_kernel<<<(N + 255) / 256, 256>>>(N);
    cudaEventRecord(evScan, 0);

    // gemm1 (needs nsrc only) overlaps with fill on stream 2
    cudaStreamWaitEvent(s2, evScan, 0);
    gemm1_kernel<<<(N + 63) / 64, 256, 0, s2>>>(feat, W1, N);
    cudaEventRecord(evGemm, s2);

    fill_kernel<<<(E + 255) / 256, 256>>>(src, dst, E);
    cudaStreamWaitEvent(0, evGemm, 0);

    int gblocks = (N * 32 + 255) / 256;
    gather1_kernel<<<gblocks, 256>>>(b1, N);
    gather2_kernel<<<gblocks, 256>>>(N);

    final_kernel<<<(N + 63) / 64, 256>>>(noise, W_mu, b_mu, W_sig, b_sig,
                                         (float*)d_out, N);
}

// round 13
// speedup vs baseline: 1.0462x; 1.0462x over previous
#include <cuda_runtime.h>
#include <cuda_fp16.h>
#include <mma.h>
#include <math.h>

using namespace nvcuda;

#define NN 100000
#define EE 1600000
#define FD 128
#define HD 64
#define CSR_CAP (EE + 3 * NN + 8)

// Scratch (device globals)
__device__ int    g_cnt[2 * NN + 32];       // [0..NN)=out, [NN..2NN)=in, [2NN]=scan ticket
__device__ float  g_nsrc[NN];
__device__ float  g_ndst[NN];
__device__ int    g_off[NN];
__device__ int    g_cursor[NN];
__device__ int    g_csr[CSR_CAP];           // padded to mult-of-4 per node; sentinel = NN
__device__ __half g_x16[(size_t)(NN + 1) * HD];  // row NN = zero sentinel
__device__ __half g_y16[(size_t)(NN + 1) * HD];  // row NN = zero sentinel
__device__ __half g_a16[(size_t)NN * HD];

// ---------------------------------------------------------------------------
// Degrees (R4-proven: 4 edges/thread)
// ---------------------------------------------------------------------------
__global__ void deg_kernel(const int* __restrict__ src, const int* __restrict__ dst, int E) {
    int i = (blockIdx.x * blockDim.x + threadIdx.x) * 4;
    if (i + 4 <= E) {
        int4 s = *(const int4*)(src + i);
        int4 d = *(const int4*)(dst + i);
        atomicAdd(&g_cnt[s.x], 1); atomicAdd(&g_cnt[s.y], 1);
        atomicAdd(&g_cnt[s.z], 1); atomicAdd(&g_cnt[s.w], 1);
        atomicAdd(&g_cnt[NN + d.x], 1); atomicAdd(&g_cnt[NN + d.y], 1);
        atomicAdd(&g_cnt[NN + d.z], 1); atomicAdd(&g_cnt[NN + d.w], 1);
    } else {
        for (int j = i; j < E; j++) {
            atomicAdd(&g_cnt[src[j]], 1);
            atomicAdd(&g_cnt[NN + dst[j]], 1);
        }
    }
}

// ---------------------------------------------------------------------------
// Scan + norm fused; scans PADDED degrees (mult-of-4) and writes sentinels
// into the padding slots (fill later overwrites only the first cin slots).
// ---------------------------------------------------------------------------
__global__ void __launch_bounds__(256) scan_norm_kernel(int N) {
    __shared__ int wsum[8];
    __shared__ int sbase;
    int i = blockIdx.x * 256 + threadIdx.x;
    int lane = threadIdx.x & 31, wid = threadIdx.x >> 5;

    int cin = (i < N) ? g_cnt[NN + i] : 0;
    int pad = (cin + 3) & ~3;
    int x = pad;
#pragma unroll
    for (int o = 1; o < 32; o <<= 1) {
        int n = __shfl_up_sync(0xffffffffu, x, o);
        if (lane >= o) x += n;
    }
    if (lane == 31) wsum[wid] = x;
    __syncthreads();
    if (threadIdx.x == 0) {
        int run = 0;
#pragma unroll
        for (int w = 0; w < 8; w++) { run += wsum[w]; wsum[w] = run; }
        sbase = atomicAdd(&g_cnt[2 * NN], run);
    }
    __syncthreads();
    int excl = x - pad + (wid > 0 ? wsum[wid - 1] : 0) + sbase;
    if (i < N) {
        g_off[i] = excl;
        g_cursor[i] = excl;
        g_nsrc[i] = rsqrtf(fmaxf((float)g_cnt[i], 1.0f));
        g_ndst[i] = rsqrtf(fmaxf((float)cin, 1.0f));
        for (int s = cin; s < pad; s++) g_csr[excl + s] = NN;   // zero-row sentinels
    }
}

// ---------------------------------------------------------------------------
// Fill CSR: 1 edge per thread (R4-proven)
// ---------------------------------------------------------------------------
__global__ void fill_kernel(const int* __restrict__ src, const int* __restrict__ dst, int E) {
    int i = blockIdx.x * blockDim.x + threadIdx.x;
    if (i < E) {
        int p = atomicAdd(&g_cursor[dst[i]], 1);
        g_csr[p] = src[i];
    }
}

// ---------------------------------------------------------------------------
// GEMM1 (wmma HMMA, R9-proven): x16 = fp16( (feat * nsrc) @ W1 );
// also stores zeros into sentinel row N.
// ---------------------------------------------------------------------------
__global__ void __launch_bounds__(256) gemm1_kernel(const float* __restrict__ feat,
                                                    const float* __restrict__ W1, int N) {
    __shared__ __align__(32) __half As[64][136];
    __shared__ __align__(32) __half Bs[128][72];
    int tid = threadIdx.x;
    int w = tid >> 5;
    int r0 = blockIdx.x * 64;

    for (int idx = tid; idx < 2048; idx += 256) {
        int r = idx >> 5;
        int c4 = idx & 31;
        int row = r0 + r;
        float4 v = make_float4(0.f, 0.f, 0.f, 0.f);
        float s = 0.f;
        if (row < N) {
            v = ((const float4*)(feat + (size_t)row * FD))[c4];
            s = g_nsrc[row];
        }
        __half2 h0 = __floats2half2_rn(v.x * s, v.y * s);
        __half2 h1 = __floats2half2_rn(v.z * s, v.w * s);
        uint2 pk; pk.x = *(unsigned*)&h0; pk.y = *(unsigned*)&h1;
        *(uint2*)&As[r][c4 * 4] = pk;
    }
    for (int idx = tid; idx < 2048; idx += 256) {
        int k = idx >> 4;
        int c4 = idx & 15;
        float4 v = ((const float4*)(W1 + (size_t)k * HD))[c4];
        __half2 h0 = __floats2half2_rn(v.x, v.y);
        __half2 h1 = __floats2half2_rn(v.z, v.w);
        uint2 pk; pk.x = *(unsigned*)&h0; pk.y = *(unsigned*)&h1;
        *(uint2*)&Bs[k][c4 * 4] = pk;
    }
    __syncthreads();

    int rg = w >> 1;
    int cg = (w & 1) * 2;
    wmma::fragment<wmma::accumulator, 16, 16, 16, float> c0, c1;
    wmma::fill_fragment(c0, 0.0f);
    wmma::fill_fragment(c1, 0.0f);
#pragma unroll
    for (int k = 0; k < 8; k++) {
        wmma::fragment<wmma::matrix_a, 16, 16, 16, __half, wmma::row_major> a;
        wmma::fragment<wmma::matrix_b, 16, 16, 16, __half, wmma::row_major> b0, b1;
        wmma::load_matrix_sync(a, &As[rg * 16][k * 16], 136);
        wmma::load_matrix_sync(b0, &Bs[k * 16][cg * 16], 72);
        wmma::load_matrix_sync(b1, &Bs[k * 16][(cg + 1) * 16], 72);
        wmma::mma_sync(c0, a, b0, c0);
        wmma::mma_sync(c1, a, b1, c1);
    }
    __syncthreads();

    float* Cs = (float*)&As[0][0];
    wmma::store_matrix_sync(Cs + (rg * 16) * 68 + cg * 16, c0, 68, wmma::mem_row_major);
    wmma::store_matrix_sync(Cs + (rg * 16) * 68 + (cg + 1) * 16, c1, 68, wmma::mem_row_major);
    __syncthreads();

    for (int idx = tid; idx < 1024; idx += 256) {
        int r = idx >> 4;
        int c4 = idx & 15;
        int row = r0 + r;
        if (row <= N) {     // row N: acc==0 (guarded loads) -> writes zero sentinel row
            const float* p = Cs + r * 68 + c4 * 4;
            __half2 h0 = __floats2half2_rn(p[0], p[1]);
            __half2 h1 = __floats2half2_rn(p[2], p[3]);
            uint2 pk; pk.x = *(unsigned*)&h0; pk.y = *(unsigned*)&h1;
            *(uint2*)(g_x16 + (size_t)row * HD + c4 * 4) = pk;
        }
    }
}

// ---------------------------------------------------------------------------
// Shuffle-free gather: segments are mult-of-4 with zero-row sentinels.
// Per 4 edges: 1 uniform int2 index load (per half-warp) + 2 feature LDGs
// (each instr covers 2 rows: lanes 0-15 row A, lanes 16-31 row B; 8B/lane).
// Half-warp partials merged with 4 shfl_xor at the end.
// ---------------------------------------------------------------------------
__device__ __forceinline__ void gather_row_fast(const __half* __restrict__ X,
                                                int beg, int end, int g, int sl,
                                                float acc[4]) {
#pragma unroll 2
    for (int j = beg; j < end; j += 4) {
        int2 rr = *(const int2*)&g_csr[j + 2 * g];   // warp-uniform per half
        uint2 q0 = *(const uint2*)(X + (size_t)rr.x * HD + sl * 4);
        uint2 q1 = *(const uint2*)(X + (size_t)rr.y * HD + sl * 4);
        float2 a0 = __half22float2(*(__half2*)&q0.x);
        float2 b0 = __half22float2(*(__half2*)&q0.y);
        float2 a1 = __half22float2(*(__half2*)&q1.x);
        float2 b1 = __half22float2(*(__half2*)&q1.y);
        acc[0] += a0.x + a1.x;
        acc[1] += a0.y + a1.y;
        acc[2] += b0.x + b1.x;
        acc[3] += b0.y + b1.y;
    }
#pragma unroll
    for (int k = 0; k < 4; k++)
        acc[k] += __shfl_xor_sync(0xffffffffu, acc[k], 16);
}

__global__ void __launch_bounds__(256) gather1_kernel(const float* __restrict__ b1, int N) {
    int warp = (blockIdx.x * blockDim.x + threadIdx.x) >> 5;
    int lane = threadIdx.x & 31;
    int g = lane >> 4, sl = lane & 15;
    if (warp > N) return;
    if (warp == N) {        // zero sentinel row of y16
        if (g == 0) *(uint2*)(g_y16 + (size_t)N * HD + sl * 4) = make_uint2(0u, 0u);
        return;
    }
    int beg = g_off[warp];
    int cin = g_cnt[NN + warp];
    int end = beg + ((cin + 3) & ~3);

    float acc[4] = {0.f, 0.f, 0.f, 0.f};
    gather_row_fast(g_x16, beg, end, g, sl, acc);

    float nd = g_ndst[warp];
    float ns = g_nsrc[warp];
    float4 b = *(const float4*)(b1 + sl * 4);
    float o0 = fmaxf(acc[0] * nd + b.x, 0.f) * ns;
    float o1 = fmaxf(acc[1] * nd + b.y, 0.f) * ns;
    float o2 = fmaxf(acc[2] * nd + b.z, 0.f) * ns;
    float o3 = fmaxf(acc[3] * nd + b.w, 0.f) * ns;
    if (g == 0) {
        __half2 h0 = __floats2half2_rn(o0, o1);
        __half2 h1 = __floats2half2_rn(o2, o3);
        uint2 pk; pk.x = *(unsigned*)&h0; pk.y = *(unsigned*)&h1;
        *(uint2*)(g_y16 + (size_t)warp * HD + sl * 4) = pk;
    }
}

__global__ void __launch_bounds__(256) gather2_kernel(int N) {
    int warp = (blockIdx.x * blockDim.x + threadIdx.x) >> 5;
    int lane = threadIdx.x & 31;
    int g = lane >> 4, sl = lane & 15;
    if (warp >= N) return;
    int beg = g_off[warp];
    int cin = g_cnt[NN + warp];
    int end = beg + ((cin + 3) & ~3);

    float acc[4] = {0.f, 0.f, 0.f, 0.f};
    gather_row_fast(g_y16, beg, end, g, sl, acc);

    float nd = g_ndst[warp];
    if (g == 0) {
        __half2 h0 = __floats2half2_rn(acc[0] * nd, acc[1] * nd);
        __half2 h1 = __floats2half2_rn(acc[2] * nd, acc[3] * nd);
        uint2 pk; pk.x = *(unsigned*)&h0; pk.y = *(unsigned*)&h1;
        *(uint2*)(g_a16 + (size_t)warp * HD + sl * 4) = pk;
    }
}

// ---------------------------------------------------------------------------
// Final (wmma HMMA dual-GEMM, R9-proven) with __expf epilogue
// ---------------------------------------------------------------------------
__global__ void __launch_bounds__(256) final_kernel(const float* __restrict__ noise,
                                                    const float* __restrict__ W_mu,
                                                    const float* __restrict__ b_mu,
                                                    const float* __restrict__ W_sig,
                                                    const float* __restrict__ b_sig,
                                                    float* __restrict__ out, int N) {
    __shared__ __align__(32) char sbuf[64 * 132 * 4];    // 33792 B union
    __half* As = (__half*)sbuf;                          // [64][72]  = 9216 B
    __half* Bs = (__half*)(sbuf + 9216);                 // [64][136] = 17408 B
    float*  Cs = (float*)sbuf;                           // [64][132] (after mma)
    int tid = threadIdx.x;
    int w = tid >> 5;
    int r0 = blockIdx.x * 64;

    for (int idx = tid; idx < 1024; idx += 256) {
        int r = idx >> 4;
        int c4 = idx & 15;
        int row = r0 + r;
        uint2 pk = make_uint2(0u, 0u);
        if (row < N) pk = *(const uint2*)(g_a16 + (size_t)row * HD + c4 * 4);
        *(uint2*)&As[r * 72 + c4 * 4] = pk;
    }
    for (int idx = tid; idx < 2048; idx += 256) {
        int k = idx >> 5;
        int c4 = idx & 31;
        float4 v = (c4 < 16) ? ((const float4*)(W_mu + (size_t)k * HD))[c4]
                             : ((const float4*)(W_sig + (size_t)k * HD))[c4 - 16];
        __half2 h0 = __floats2half2_rn(v.x, v.y);
        __half2 h1 = __floats2half2_rn(v.z, v.w);
        uint2 pk; pk.x = *(unsigned*)&h0; pk.y = *(unsigned*)&h1;
        *(uint2*)&Bs[k * 136 + c4 * 4] = pk;
    }
    __syncthreads();

    int rg = w >> 1;
    int ch = (w & 1) * 4;
    wmma::fragment<wmma::accumulator, 16, 16, 16, float> c[4];
#pragma unroll
    for (int f = 0; f < 4; f++) wmma::fill_fragment(c[f], 0.0f);
#pragma unroll
    for (int k = 0; k < 4; k++) {
        wmma::fragment<wmma::matrix_a, 16, 16, 16, __half, wmma::row_major> a;
        wmma::load_matrix_sync(a, &As[rg * 16 * 72 + k * 16], 72);
#pragma unroll
        for (int f = 0; f < 4; f++) {
            wmma::fragment<wmma::matrix_b, 16, 16, 16, __half, wmma::row_major> b;
            wmma::load_matrix_sync(b, &Bs[k * 16 * 136 + (ch + f) * 16], 136);
            wmma::mma_sync(c[f], a, b, c[f]);
        }
    }
    __syncthreads();
#pragma unroll
    for (int f = 0; f < 4; f++)
        wmma::store_matrix_sync(Cs + (rg * 16) * 132 + (ch + f) * 16, c[f], 132,
                                wmma::mem_row_major);
    __syncthreads();

    int tx = tid & 15, ty = tid >> 4;
    float4 bm = *(const float4*)(b_mu + tx * 4);
    float4 bsg = *(const float4*)(b_sig + tx * 4);
#pragma unroll
    for (int i = 0; i < 4; i++) {
        int r = ty * 4 + i;
        int row = r0 + r;
        if (row < N) {
            const float* pm = Cs + r * 132 + tx * 4;
            const float* ps = Cs + r * 132 + 64 + tx * 4;
            float4 nz = *(const float4*)(noise + (size_t)row * HD + tx * 4);
            float4 o;
            o.x = (pm[0] + bm.x) + nz.x * __expf(ps[0] + bsg.x);
            o.y = (pm[1] + bm.y) + nz.y * __expf(ps[1] + bsg.y);
            o.z = (pm[2] + bm.z) + nz.z * __expf(ps[2] + bsg.z);
            o.w = (pm[3] + bm.w) + nz.w * __expf(ps[3] + bsg.w);
            *(float4*)(out + (size_t)row * HD + tx * 4) = o;
        }
    }
}

// ---------------------------------------------------------------------------
// Launch — exact R9 structure
// ---------------------------------------------------------------------------
static cudaStream_t s2 = nullptr;
static cudaEvent_t  evScan = nullptr, evGemm = nullptr;

extern "C" void kernel_launch(void* const* d_in, const int* in_sizes, int n_in,
                              void* d_out, int out_size) {
    const float* feat  = (const float*)d_in[0];
    const int*   src   = (const int*)d_in[1];
    const int*   dst   = (const int*)d_in[2];
    const float* noise = (const float*)d_in[3];
    const float* W1    = (const float*)d_in[4];
    const float* b1    = (const float*)d_in[5];
    const float* W_mu  = (const float*)d_in[6];
    const float* b_mu  = (const float*)d_in[7];
    const float* W_sig = (const float*)d_in[8];
    const float* b_sig = (const float*)d_in[9];

    int N = in_sizes[0] / FD;
    int E = in_sizes[1];

    if (s2 == nullptr) {
        cudaStreamCreateWithFlags(&s2, cudaStreamNonBlocking);
        cudaEventCreateWithFlags(&evScan, cudaEventDisableTiming);
        cudaEventCreateWithFlags(&evGemm, cudaEventDisableTiming);
    }

    void* p_cnt;
    cudaGetSymbolAddress(&p_cnt, g_cnt);
    cudaMemsetAsync(p_cnt, 0, sizeof(int) * (2 * NN + 32));

    deg_kernel<<<(E / 4 + 255) / 256, 256>>>(src, dst, E);
    scan_norm_kernel<<<(N + 255) / 256, 256>>>(N);
    cudaEventRecord(evScan, 0);

    // gemm1 (needs nsrc only) overlaps with fill on stream 2
    cudaStreamWaitEvent(s2, evScan, 0);
    gemm1_kernel<<<(N + 63) / 64, 256, 0, s2>>>(feat, W1, N);
    cudaEventRecord(evGemm, s2);

    fill_kernel<<<(E + 255) / 256, 256>>>(src, dst, E);
    cudaStreamWaitEvent(0, evGemm, 0);

    int gblocks = ((N + 1) * 32 + 255) / 256;   // +1 warp zeroes y16 sentinel row
    gather1_kernel<<<gblocks, 256>>>(b1, N);
    gather2_kernel<<<gblocks, 256>>>(N);

    final_kernel<<<(N + 63) / 64, 256>>>(noise, W_mu, b_mu, W_sig, b_sig,
                                         (float*)d_out, N);
}

// round 14
// speedup vs baseline: 1.0566x; 1.0099x over previous
#include <cuda_runtime.h>
#include <cuda_fp16.h>
#include <mma.h>
#include <math.h>

using namespace nvcuda;

#define NN 100000
#define EE 1600000
#define FD 128
#define HD 64
#define CSR_CAP (EE + 3 * NN + 8)

// Scratch (device globals; zero at module load, re-zeroed by tail zero_kernel)
__device__ int    g_cnt[2 * NN + 32];       // [0..NN)=out, [NN..2NN)=in, [2NN]=scan ticket
__device__ float  g_nsrc[NN];
__device__ float  g_ndst[NN];
__device__ int    g_off[NN];
__device__ int    g_cursor[NN];
__device__ int    g_csr[CSR_CAP];           // padded to mult-of-4 per node; sentinel = NN
__device__ __half g_x16[(size_t)(NN + 1) * HD];  // row NN = zero sentinel
__device__ __half g_y16[(size_t)(NN + 1) * HD];  // row NN = zero sentinel
__device__ __half g_a16[(size_t)NN * HD];

// ---------------------------------------------------------------------------
// Degrees (R4-proven: 4 edges/thread). Counters are pre-zeroed (load-time BSS
// zero on the first call; tail zero_kernel on every subsequent sequence).
// ---------------------------------------------------------------------------
__global__ void deg_kernel(const int* __restrict__ src, const int* __restrict__ dst, int E) {
    int i = (blockIdx.x * blockDim.x + threadIdx.x) * 4;
    if (i + 4 <= E) {
        int4 s = *(const int4*)(src + i);
        int4 d = *(const int4*)(dst + i);
        atomicAdd(&g_cnt[s.x], 1); atomicAdd(&g_cnt[s.y], 1);
        atomicAdd(&g_cnt[s.z], 1); atomicAdd(&g_cnt[s.w], 1);
        atomicAdd(&g_cnt[NN + d.x], 1); atomicAdd(&g_cnt[NN + d.y], 1);
        atomicAdd(&g_cnt[NN + d.z], 1); atomicAdd(&g_cnt[NN + d.w], 1);
    } else {
        for (int j = i; j < E; j++) {
            atomicAdd(&g_cnt[src[j]], 1);
            atomicAdd(&g_cnt[NN + dst[j]], 1);
        }
    }
}

// ---------------------------------------------------------------------------
// Scan + norm fused; scans PADDED degrees (mult-of-4), writes sentinels
// ---------------------------------------------------------------------------
__global__ void __launch_bounds__(256) scan_norm_kernel(int N) {
    __shared__ int wsum[8];
    __shared__ int sbase;
    int i = blockIdx.x * 256 + threadIdx.x;
    int lane = threadIdx.x & 31, wid = threadIdx.x >> 5;

    int cin = (i < N) ? g_cnt[NN + i] : 0;
    int pad = (cin + 3) & ~3;
    int x = pad;
#pragma unroll
    for (int o = 1; o < 32; o <<= 1) {
        int n = __shfl_up_sync(0xffffffffu, x, o);
        if (lane >= o) x += n;
    }
    if (lane == 31) wsum[wid] = x;
    __syncthreads();
    if (threadIdx.x == 0) {
        int run = 0;
#pragma unroll
        for (int w = 0; w < 8; w++) { run += wsum[w]; wsum[w] = run; }
        sbase = atomicAdd(&g_cnt[2 * NN], run);
    }
    __syncthreads();
    int excl = x - pad + (wid > 0 ? wsum[wid - 1] : 0) + sbase;
    if (i < N) {
        g_off[i] = excl;
        g_cursor[i] = excl;
        g_nsrc[i] = rsqrtf(fmaxf((float)g_cnt[i], 1.0f));
        g_ndst[i] = rsqrtf(fmaxf((float)cin, 1.0f));
        for (int s = cin; s < pad; s++) g_csr[excl + s] = NN;   // zero-row sentinels
    }
}

// ---------------------------------------------------------------------------
// Fill CSR: 1 edge per thread (R4-proven)
// ---------------------------------------------------------------------------
__global__ void fill_kernel(const int* __restrict__ src, const int* __restrict__ dst, int E) {
    int i = blockIdx.x * blockDim.x + threadIdx.x;
    if (i < E) {
        int p = atomicAdd(&g_cursor[dst[i]], 1);
        g_csr[p] = src[i];
    }
}

// ---------------------------------------------------------------------------
// GEMM1 (wmma HMMA, R9-proven): x16 = fp16( (feat * nsrc) @ W1 );
// also stores zeros into sentinel row N.
// ---------------------------------------------------------------------------
__global__ void __launch_bounds__(256) gemm1_kernel(const float* __restrict__ feat,
                                                    const float* __restrict__ W1, int N) {
    __shared__ __align__(32) __half As[64][136];
    __shared__ __align__(32) __half Bs[128][72];
    int tid = threadIdx.x;
    int w = tid >> 5;
    int r0 = blockIdx.x * 64;

    for (int idx = tid; idx < 2048; idx += 256) {
        int r = idx >> 5;
        int c4 = idx & 31;
        int row = r0 + r;
        float4 v = make_float4(0.f, 0.f, 0.f, 0.f);
        float s = 0.f;
        if (row < N) {
            v = ((const float4*)(feat + (size_t)row * FD))[c4];
            s = g_nsrc[row];
        }
        __half2 h0 = __floats2half2_rn(v.x * s, v.y * s);
        __half2 h1 = __floats2half2_rn(v.z * s, v.w * s);
        uint2 pk; pk.x = *(unsigned*)&h0; pk.y = *(unsigned*)&h1;
        *(uint2*)&As[r][c4 * 4] = pk;
    }
    for (int idx = tid; idx < 2048; idx += 256) {
        int k = idx >> 4;
        int c4 = idx & 15;
        float4 v = ((const float4*)(W1 + (size_t)k * HD))[c4];
        __half2 h0 = __floats2half2_rn(v.x, v.y);
        __half2 h1 = __floats2half2_rn(v.z, v.w);
        uint2 pk; pk.x = *(unsigned*)&h0; pk.y = *(unsigned*)&h1;
        *(uint2*)&Bs[k][c4 * 4] = pk;
    }
    __syncthreads();

    int rg = w >> 1;
    int cg = (w & 1) * 2;
    wmma::fragment<wmma::accumulator, 16, 16, 16, float> c0, c1;
    wmma::fill_fragment(c0, 0.0f);
    wmma::fill_fragment(c1, 0.0f);
#pragma unroll
    for (int k = 0; k < 8; k++) {
        wmma::fragment<wmma::matrix_a, 16, 16, 16, __half, wmma::row_major> a;
        wmma::fragment<wmma::matrix_b, 16, 16, 16, __half, wmma::row_major> b0, b1;
        wmma::load_matrix_sync(a, &As[rg * 16][k * 16], 136);
        wmma::load_matrix_sync(b0, &Bs[k * 16][cg * 16], 72);
        wmma::load_matrix_sync(b1, &Bs[k * 16][(cg + 1) * 16], 72);
        wmma::mma_sync(c0, a, b0, c0);
        wmma::mma_sync(c1, a, b1, c1);
    }
    __syncthreads();

    float* Cs = (float*)&As[0][0];
    wmma::store_matrix_sync(Cs + (rg * 16) * 68 + cg * 16, c0, 68, wmma::mem_row_major);
    wmma::store_matrix_sync(Cs + (rg * 16) * 68 + (cg + 1) * 16, c1, 68, wmma::mem_row_major);
    __syncthreads();

    for (int idx = tid; idx < 1024; idx += 256) {
        int r = idx >> 4;
        int c4 = idx & 15;
        int row = r0 + r;
        if (row <= N) {     // row N: acc==0 (guarded loads) -> writes zero sentinel row
            const float* p = Cs + r * 68 + c4 * 4;
            __half2 h0 = __floats2half2_rn(p[0], p[1]);
            __half2 h1 = __floats2half2_rn(p[2], p[3]);
            uint2 pk; pk.x = *(unsigned*)&h0; pk.y = *(unsigned*)&h1;
            *(uint2*)(g_x16 + (size_t)row * HD + c4 * 4) = pk;
        }
    }
}

// ---------------------------------------------------------------------------
// Shuffle-free gather (R13-proven): mult-of-4 segments, zero-row sentinels.
// ---------------------------------------------------------------------------
__device__ __forceinline__ void gather_row_fast(const __half* __restrict__ X,
                                                int beg, int end, int g, int sl,
                                                float acc[4]) {
#pragma unroll 2
    for (int j = beg; j < end; j += 4) {
        int2 rr = *(const int2*)&g_csr[j + 2 * g];   // warp-uniform per half
        uint2 q0 = *(const uint2*)(X + (size_t)rr.x * HD + sl * 4);
        uint2 q1 = *(const uint2*)(X + (size_t)rr.y * HD + sl * 4);
        float2 a0 = __half22float2(*(__half2*)&q0.x);
        float2 b0 = __half22float2(*(__half2*)&q0.y);
        float2 a1 = __half22float2(*(__half2*)&q1.x);
        float2 b1 = __half22float2(*(__half2*)&q1.y);
        acc[0] += a0.x + a1.x;
        acc[1] += a0.y + a1.y;
        acc[2] += b0.x + b1.x;
        acc[3] += b0.y + b1.y;
    }
#pragma unroll
    for (int k = 0; k < 4; k++)
        acc[k] += __shfl_xor_sync(0xffffffffu, acc[k], 16);
}

__global__ void __launch_bounds__(256) gather1_kernel(const float* __restrict__ b1, int N) {
    int warp = (blockIdx.x * blockDim.x + threadIdx.x) >> 5;
    int lane = threadIdx.x & 31;
    int g = lane >> 4, sl = lane & 15;
    if (warp > N) return;
    if (warp == N) {        // zero sentinel row of y16
        if (g == 0) *(uint2*)(g_y16 + (size_t)N * HD + sl * 4) = make_uint2(0u, 0u);
        return;
    }
    int beg = g_off[warp];
    int cin = g_cnt[NN + warp];
    int end = beg + ((cin + 3) & ~3);

    float acc[4] = {0.f, 0.f, 0.f, 0.f};
    gather_row_fast(g_x16, beg, end, g, sl, acc);

    float nd = g_ndst[warp];
    float ns = g_nsrc[warp];
    float4 b = *(const float4*)(b1 + sl * 4);
    float o0 = fmaxf(acc[0] * nd + b.x, 0.f) * ns;
    float o1 = fmaxf(acc[1] * nd + b.y, 0.f) * ns;
    float o2 = fmaxf(acc[2] * nd + b.z, 0.f) * ns;
    float o3 = fmaxf(acc[3] * nd + b.w, 0.f) * ns;
    if (g == 0) {
        __half2 h0 = __floats2half2_rn(o0, o1);
        __half2 h1 = __floats2half2_rn(o2, o3);
        uint2 pk; pk.x = *(unsigned*)&h0; pk.y = *(unsigned*)&h1;
        *(uint2*)(g_y16 + (size_t)warp * HD + sl * 4) = pk;
    }
}

__global__ void __launch_bounds__(256) gather2_kernel(int N) {
    int warp = (blockIdx.x * blockDim.x + threadIdx.x) >> 5;
    int lane = threadIdx.x & 31;
    int g = lane >> 4, sl = lane & 15;
    if (warp >= N) return;
    int beg = g_off[warp];
    int cin = g_cnt[NN + warp];
    int end = beg + ((cin + 3) & ~3);

    float acc[4] = {0.f, 0.f, 0.f, 0.f};
    gather_row_fast(g_y16, beg, end, g, sl, acc);

    float nd = g_ndst[warp];
    if (g == 0) {
        __half2 h0 = __floats2half2_rn(acc[0] * nd, acc[1] * nd);
        __half2 h1 = __floats2half2_rn(acc[2] * nd, acc[3] * nd);
        uint2 pk; pk.x = *(unsigned*)&h0; pk.y = *(unsigned*)&h1;
        *(uint2*)(g_a16 + (size_t)warp * HD + sl * 4) = pk;
    }
}

// ---------------------------------------------------------------------------
// Final (wmma HMMA dual-GEMM, R9-proven) with __expf epilogue
// ---------------------------------------------------------------------------
__global__ void __launch_bounds__(256) final_kernel(const float* __restrict__ noise,
                                                    const float* __restrict__ W_mu,
                                                    const float* __restrict__ b_mu,
                                                    const float* __restrict__ W_sig,
                                                    const float* __restrict__ b_sig,
                                                    float* __restrict__ out, int N) {
    __shared__ __align__(32) char sbuf[64 * 132 * 4];    // 33792 B union
    __half* As = (__half*)sbuf;                          // [64][72]  = 9216 B
    __half* Bs = (__half*)(sbuf + 9216);                 // [64][136] = 17408 B
    float*  Cs = (float*)sbuf;                           // [64][132] (after mma)
    int tid = threadIdx.x;
    int w = tid >> 5;
    int r0 = blockIdx.x * 64;

    for (int idx = tid; idx < 1024; idx += 256) {
        int r = idx >> 4;
        int c4 = idx & 15;
        int row = r0 + r;
        uint2 pk = make_uint2(0u, 0u);
        if (row < N) pk = *(const uint2*)(g_a16 + (size_t)row * HD + c4 * 4);
        *(uint2*)&As[r * 72 + c4 * 4] = pk;
    }
    for (int idx = tid; idx < 2048; idx += 256) {
        int k = idx >> 5;
        int c4 = idx & 31;
        float4 v = (c4 < 16) ? ((const float4*)(W_mu + (size_t)k * HD))[c4]
                             : ((const float4*)(W_sig + (size_t)k * HD))[c4 - 16];
        __half2 h0 = __floats2half2_rn(v.x, v.y);
        __half2 h1 = __floats2half2_rn(v.z, v.w);
        uint2 pk; pk.x = *(unsigned*)&h0; pk.y = *(unsigned*)&h1;
        *(uint2*)&Bs[k * 136 + c4 * 4] = pk;
    }
    __syncthreads();

    int rg = w >> 1;
    int ch = (w & 1) * 4;
    wmma::fragment<wmma::accumulator, 16, 16, 16, float> c[4];
#pragma unroll
    for (int f = 0; f < 4; f++) wmma::fill_fragment(c[f], 0.0f);
#pragma unroll
    for (int k = 0; k < 4; k++) {
        wmma::fragment<wmma::matrix_a, 16, 16, 16, __half, wmma::row_major> a;
        wmma::load_matrix_sync(a, &As[rg * 16 * 72 + k * 16], 72);
#pragma unroll
        for (int f = 0; f < 4; f++) {
            wmma::fragment<wmma::matrix_b, 16, 16, 16, __half, wmma::row_major> b;
            wmma::load_matrix_sync(b, &Bs[k * 16 * 136 + (ch + f) * 16], 136);
            wmma::mma_sync(c[f], a, b, c[f]);
        }
    }
    __syncthreads();
#pragma unroll
    for (int f = 0; f < 4; f++)
        wmma::store_matrix_sync(Cs + (rg * 16) * 132 + (ch + f) * 16, c[f], 132,
                                wmma::mem_row_major);
    __syncthreads();

    int tx = tid & 15, ty = tid >> 4;
    float4 bm = *(const float4*)(b_mu + tx * 4);
    float4 bsg = *(const float4*)(b_sig + tx * 4);
#pragma unroll
    for (int i = 0; i < 4; i++) {
        int r = ty * 4 + i;
        int row = r0 + r;
        if (row < N) {
            const float* pm = Cs + r * 132 + tx * 4;
            const float* ps = Cs + r * 132 + 64 + tx * 4;
            float4 nz = *(const float4*)(noise + (size_t)row * HD + tx * 4);
            float4 o;
            o.x = (pm[0] + bm.x) + nz.x * __expf(ps[0] + bsg.x);
            o.y = (pm[1] + bm.y) + nz.y * __expf(ps[1] + bsg.y);
            o.z = (pm[2] + bm.z) + nz.z * __expf(ps[2] + bsg.z);
            o.w = (pm[3] + bm.w) + nz.w * __expf(ps[3] + bsg.w);
            *(float4*)(out + (size_t)row * HD + tx * 4) = o;
        }
    }
}

// ---------------------------------------------------------------------------
// Tail zeroing: re-zero counters + ticket for the NEXT sequence run.
// (BSS is zero at module load, so the first run is also clean.)
// ---------------------------------------------------------------------------
__global__ void zero_kernel() {
    int i = blockIdx.x * blockDim.x + threadIdx.x;
    const int n4 = (2 * NN + 32) / 4;
    if (i < n4) ((int4*)g_cnt)[i] = make_int4(0, 0, 0, 0);
}

// ---------------------------------------------------------------------------
// Launch — R13 structure, head memset replaced by tail zero_kernel
// ---------------------------------------------------------------------------
static cudaStream_t s2 = nullptr;
static cudaEvent_t  evScan = nullptr, evGemm = nullptr;

extern "C" void kernel_launch(void* const* d_in, const int* in_sizes, int n_in,
                              void* d_out, int out_size) {
    const float* feat  = (const float*)d_in[0];
    const int*   src   = (const int*)d_in[1];
    const int*   dst   = (const int*)d_in[2];
    const float* noise = (const float*)d_in[3];
    const float* W1    = (const float*)d_in[4];
    const float* b1    = (const float*)d_in[5];
    const float* W_mu  = (const float*)d_in[6];
    const float* b_mu  = (const float*)d_in[7];
    const float* W_sig = (const float*)d_in[8];
    const float* b_sig = (const float*)d_in[9];

    int N = in_sizes[0] / FD;
    int E = in_sizes[1];

    if (s2 == nullptr) {
        cudaStreamCreateWithFlags(&s2, cudaStreamNonBlocking);
        cudaEventCreateWithFlags(&evScan, cudaEventDisableTiming);
        cudaEventCreateWithFlags(&evGemm, cudaEventDisableTiming);
    }

    deg_kernel<<<(E / 4 + 255) / 256, 256>>>(src, dst, E);
    scan_norm_kernel<<<(N + 255) / 256, 256>>>(N);
    cudaEventRecord(evScan, 0);

    // gemm1 (needs nsrc only) overlaps with fill on stream 2
    cudaStreamWaitEvent(s2, evScan, 0);
    gemm1_kernel<<<(N + 63) / 64, 256, 0, s2>>>(feat, W1, N);
    cudaEventRecord(evGemm, s2);

    fill_kernel<<<(E + 255) / 256, 256>>>(src, dst, E);
    cudaStreamWaitEvent(0, evGemm, 0);

    int gblocks = ((N + 1) * 32 + 255) / 256;   // +1 warp zeroes y16 sentinel row
    gather1_kernel<<<gblocks, 256>>>(b1, N);
    gather2_kernel<<<gblocks, 256>>>(N);

    final_kernel<<<(N + 63) / 64, 256>>>(noise, W_mu, b_mu, W_sig, b_sig,
                                         (float*)d_out, N);

    // Re-zero counters for the next replay (tail, off the critical head)
    zero_kernel<<<((2 * NN + 32) / 4 + 255) / 256, 256>>>();
}

// round 15
// speedup vs baseline: 1.0965x; 1.0378x over previous
#include <cuda_runtime.h>
#include <cuda_fp16.h>
#include <mma.h>
#include <math.h>

using namespace nvcuda;

#define NN 100000
#define EE 1600000
#define FD 128
#define HD 64
#define CSR_CAP (EE + 7 * NN + 16)

// Scratch (device globals; zero at module load, re-zeroed by tail zero_kernel)
__device__ int    g_cnt[2 * NN + 32];       // [0..NN)=out, [NN..2NN)=in, [2NN]=scan ticket
__device__ float  g_nsrc[NN];
__device__ float  g_ndst[NN];
__device__ int    g_off[NN];
__device__ int    g_rank[EE];               // per-edge arrival rank within dst segment
__device__ int    g_csr[CSR_CAP];           // padded to mult-of-8 per node; sentinel = NN
__device__ __half g_x16[(size_t)(NN + 1) * HD];  // row NN = zero sentinel
__device__ __half g_y16[(size_t)(NN + 1) * HD];  // row NN = zero sentinel
__device__ __half g_a16[(size_t)NN * HD];

// ---------------------------------------------------------------------------
// Degrees + per-edge rank (atomicAdd return value, previously discarded).
// 4 edges/thread (R4-proven shape).
// ---------------------------------------------------------------------------
__global__ void deg_kernel(const int* __restrict__ src, const int* __restrict__ dst, int E) {
    int i = (blockIdx.x * blockDim.x + threadIdx.x) * 4;
    if (i + 4 <= E) {
        int4 s = *(const int4*)(src + i);
        int4 d = *(const int4*)(dst + i);
        atomicAdd(&g_cnt[s.x], 1); atomicAdd(&g_cnt[s.y], 1);
        atomicAdd(&g_cnt[s.z], 1); atomicAdd(&g_cnt[s.w], 1);
        int4 r;
        r.x = atomicAdd(&g_cnt[NN + d.x], 1);
        r.y = atomicAdd(&g_cnt[NN + d.y], 1);
        r.z = atomicAdd(&g_cnt[NN + d.z], 1);
        r.w = atomicAdd(&g_cnt[NN + d.w], 1);
        *(int4*)(g_rank + i) = r;
    } else {
        for (int j = i; j < E; j++) {
            atomicAdd(&g_cnt[src[j]], 1);
            g_rank[j] = atomicAdd(&g_cnt[NN + dst[j]], 1);
        }
    }
}

// ---------------------------------------------------------------------------
// Scan + norm fused; scans PADDED degrees (mult-of-8), writes sentinels
// ---------------------------------------------------------------------------
__global__ void __launch_bounds__(256) scan_norm_kernel(int N) {
    __shared__ int wsum[8];
    __shared__ int sbase;
    int i = blockIdx.x * 256 + threadIdx.x;
    int lane = threadIdx.x & 31, wid = threadIdx.x >> 5;

    int cin = (i < N) ? g_cnt[NN + i] : 0;
    int pad = (cin + 7) & ~7;
    int x = pad;
#pragma unroll
    for (int o = 1; o < 32; o <<= 1) {
        int n = __shfl_up_sync(0xffffffffu, x, o);
        if (lane >= o) x += n;
    }
    if (lane == 31) wsum[wid] = x;
    __syncthreads();
    if (threadIdx.x == 0) {
        int run = 0;
#pragma unroll
        for (int w = 0; w < 8; w++) { run += wsum[w]; wsum[w] = run; }
        sbase = atomicAdd(&g_cnt[2 * NN], run);
    }
    __syncthreads();
    int excl = x - pad + (wid > 0 ? wsum[wid - 1] : 0) + sbase;
    if (i < N) {
        g_off[i] = excl;
        g_nsrc[i] = rsqrtf(fmaxf((float)g_cnt[i], 1.0f));
        g_ndst[i] = rsqrtf(fmaxf((float)cin, 1.0f));
        for (int s = cin; s < pad; s++) g_csr[excl + s] = NN;   // zero-row sentinels
    }
}

// ---------------------------------------------------------------------------
// Fill CSR: ATOMIC-FREE — slot is off[dst] + precomputed rank.
// ---------------------------------------------------------------------------
__global__ void fill_kernel(const int* __restrict__ src, const int* __restrict__ dst, int E) {
    int i = blockIdx.x * blockDim.x + threadIdx.x;
    if (i < E) {
        int d = dst[i];
        g_csr[g_off[d] + g_rank[i]] = src[i];
    }
}

// ---------------------------------------------------------------------------
// GEMM1 (wmma HMMA, R9-proven): x16 = fp16( (feat * nsrc) @ W1 );
// also stores zeros into sentinel row N.
// ---------------------------------------------------------------------------
__global__ void __launch_bounds__(256) gemm1_kernel(const float* __restrict__ feat,
                                                    const float* __restrict__ W1, int N) {
    __shared__ __align__(32) __half As[64][136];
    __shared__ __align__(32) __half Bs[128][72];
    int tid = threadIdx.x;
    int w = tid >> 5;
    int r0 = blockIdx.x * 64;

    for (int idx = tid; idx < 2048; idx += 256) {
        int r = idx >> 5;
        int c4 = idx & 31;
        int row = r0 + r;
        float4 v = make_float4(0.f, 0.f, 0.f, 0.f);
        float s = 0.f;
        if (row < N) {
            v = ((const float4*)(feat + (size_t)row * FD))[c4];
            s = g_nsrc[row];
        }
        __half2 h0 = __floats2half2_rn(v.x * s, v.y * s);
        __half2 h1 = __floats2half2_rn(v.z * s, v.w * s);
        uint2 pk; pk.x = *(unsigned*)&h0; pk.y = *(unsigned*)&h1;
        *(uint2*)&As[r][c4 * 4] = pk;
    }
    for (int idx = tid; idx < 2048; idx += 256) {
        int k = idx >> 4;
        int c4 = idx & 15;
        float4 v = ((const float4*)(W1 + (size_t)k * HD))[c4];
        __half2 h0 = __floats2half2_rn(v.x, v.y);
        __half2 h1 = __floats2half2_rn(v.z, v.w);
        uint2 pk; pk.x = *(unsigned*)&h0; pk.y = *(unsigned*)&h1;
        *(uint2*)&Bs[k][c4 * 4] = pk;
    }
    __syncthreads();

    int rg = w >> 1;
    int cg = (w & 1) * 2;
    wmma::fragment<wmma::accumulator, 16, 16, 16, float> c0, c1;
    wmma::fill_fragment(c0, 0.0f);
    wmma::fill_fragment(c1, 0.0f);
#pragma unroll
    for (int k = 0; k < 8; k++) {
        wmma::fragment<wmma::matrix_a, 16, 16, 16, __half, wmma::row_major> a;
        wmma::fragment<wmma::matrix_b, 16, 16, 16, __half, wmma::row_major> b0, b1;
        wmma::load_matrix_sync(a, &As[rg * 16][k * 16], 136);
        wmma::load_matrix_sync(b0, &Bs[k * 16][cg * 16], 72);
        wmma::load_matrix_sync(b1, &Bs[k * 16][(cg + 1) * 16], 72);
        wmma::mma_sync(c0, a, b0, c0);
        wmma::mma_sync(c1, a, b1, c1);
    }
    __syncthreads();

    float* Cs = (float*)&As[0][0];
    wmma::store_matrix_sync(Cs + (rg * 16) * 68 + cg * 16, c0, 68, wmma::mem_row_major);
    wmma::store_matrix_sync(Cs + (rg * 16) * 68 + (cg + 1) * 16, c1, 68, wmma::mem_row_major);
    __syncthreads();

    for (int idx = tid; idx < 1024; idx += 256) {
        int r = idx >> 4;
        int c4 = idx & 15;
        int row = r0 + r;
        if (row <= N) {     // row N: acc==0 (guarded loads) -> writes zero sentinel row
            const float* p = Cs + r * 68 + c4 * 4;
            __half2 h0 = __floats2half2_rn(p[0], p[1]);
            __half2 h1 = __floats2half2_rn(p[2], p[3]);
            uint2 pk; pk.x = *(unsigned*)&h0; pk.y = *(unsigned*)&h1;
            *(uint2*)(g_x16 + (size_t)row * HD + c4 * 4) = pk;
        }
    }
}

// ---------------------------------------------------------------------------
// Shuffle-free gather, 8 edges/iter: per half-warp one int4 index load
// (uniform, 16B-aligned since beg is mult-of-8 ints) + 4 feature LDGs.
// ---------------------------------------------------------------------------
__device__ __forceinline__ void gather_row_fast(const __half* __restrict__ X,
                                                int beg, int end, int g, int sl,
                                                float acc[4]) {
#pragma unroll 2
    for (int j = beg; j < end; j += 8) {
        int4 rr = *(const int4*)&g_csr[j + 4 * g];   // warp-uniform per half
        uint2 q0 = *(const uint2*)(X + (size_t)rr.x * HD + sl * 4);
        uint2 q1 = *(const uint2*)(X + (size_t)rr.y * HD + sl * 4);
        uint2 q2 = *(const uint2*)(X + (size_t)rr.z * HD + sl * 4);
        uint2 q3 = *(const uint2*)(X + (size_t)rr.w * HD + sl * 4);
        float2 a0 = __half22float2(*(__half2*)&q0.x);
        float2 b0 = __half22float2(*(__half2*)&q0.y);
        float2 a1 = __half22float2(*(__half2*)&q1.x);
        float2 b1 = __half22float2(*(__half2*)&q1.y);
        float2 a2 = __half22float2(*(__half2*)&q2.x);
        float2 b2 = __half22float2(*(__half2*)&q2.y);
        float2 a3 = __half22float2(*(__half2*)&q3.x);
        float2 b3 = __half22float2(*(__half2*)&q3.y);
        acc[0] += (a0.x + a1.x) + (a2.x + a3.x);
        acc[1] += (a0.y + a1.y) + (a2.y + a3.y);
        acc[2] += (b0.x + b1.x) + (b2.x + b3.x);
        acc[3] += (b0.y + b1.y) + (b2.y + b3.y);
    }
#pragma unroll
    for (int k = 0; k < 4; k++)
        acc[k] += __shfl_xor_sync(0xffffffffu, acc[k], 16);
}

__global__ void __launch_bounds__(256) gather1_kernel(const float* __restrict__ b1, int N) {
    int warp = (blockIdx.x * blockDim.x + threadIdx.x) >> 5;
    int lane = threadIdx.x & 31;
    int g = lane >> 4, sl = lane & 15;
    if (warp > N) return;
    if (warp == N) {        // zero sentinel row of y16
        if (g == 0) *(uint2*)(g_y16 + (size_t)N * HD + sl * 4) = make_uint2(0u, 0u);
        return;
    }
    int beg = g_off[warp];
    int cin = g_cnt[NN + warp];
    int end = beg + ((cin + 7) & ~7);

    float acc[4] = {0.f, 0.f, 0.f, 0.f};
    gather_row_fast(g_x16, beg, end, g, sl, acc);

    float nd = g_ndst[warp];
    float ns = g_nsrc[warp];
    float4 b = *(const float4*)(b1 + sl * 4);
    float o0 = fmaxf(acc[0] * nd + b.x, 0.f) * ns;
    float o1 = fmaxf(acc[1] * nd + b.y, 0.f) * ns;
    float o2 = fmaxf(acc[2] * nd + b.z, 0.f) * ns;
    float o3 = fmaxf(acc[3] * nd + b.w, 0.f) * ns;
    if (g == 0) {
        __half2 h0 = __floats2half2_rn(o0, o1);
        __half2 h1 = __floats2half2_rn(o2, o3);
        uint2 pk; pk.x = *(unsigned*)&h0; pk.y = *(unsigned*)&h1;
        *(uint2*)(g_y16 + (size_t)warp * HD + sl * 4) = pk;
    }
}

__global__ void __launch_bounds__(256) gather2_kernel(int N) {
    int warp = (blockIdx.x * blockDim.x + threadIdx.x) >> 5;
    int lane = threadIdx.x & 31;
    int g = lane >> 4, sl = lane & 15;
    if (warp >= N) return;
    int beg = g_off[warp];
    int cin = g_cnt[NN + warp];
    int end = beg + ((cin + 7) & ~7);

    float acc[4] = {0.f, 0.f, 0.f, 0.f};
    gather_row_fast(g_y16, beg, end, g, sl, acc);

    float nd = g_ndst[warp];
    if (g == 0) {
        __half2 h0 = __floats2half2_rn(acc[0] * nd, acc[1] * nd);
        __half2 h1 = __floats2half2_rn(acc[2] * nd, acc[3] * nd);
        uint2 pk; pk.x = *(unsigned*)&h0; pk.y = *(unsigned*)&h1;
        *(uint2*)(g_a16 + (size_t)warp * HD + sl * 4) = pk;
    }
}

// ---------------------------------------------------------------------------
// Final (wmma HMMA dual-GEMM, R9-proven) with __expf epilogue
// ---------------------------------------------------------------------------
__global__ void __launch_bounds__(256) final_kernel(const float* __restrict__ noise,
                                                    const float* __restrict__ W_mu,
                                                    const float* __restrict__ b_mu,
                                                    const float* __restrict__ W_sig,
                                                    const float* __restrict__ b_sig,
                                                    float* __restrict__ out, int N) {
    __shared__ __align__(32) char sbuf[64 * 132 * 4];    // 33792 B union
    __half* As = (__half*)sbuf;                          // [64][72]  = 9216 B
    __half* Bs = (__half*)(sbuf + 9216);                 // [64][136] = 17408 B
    float*  Cs = (float*)sbuf;                           // [64][132] (after mma)
    int tid = threadIdx.x;
    int w = tid >> 5;
    int r0 = blockIdx.x * 64;

    for (int idx = tid; idx < 1024; idx += 256) {
        int r = idx >> 4;
        int c4 = idx & 15;
        int row = r0 + r;
        uint2 pk = make_uint2(0u, 0u);
        if (row < N) pk = *(const uint2*)(g_a16 + (size_t)row * HD + c4 * 4);
        *(uint2*)&As[r * 72 + c4 * 4] = pk;
    }
    for (int idx = tid; idx < 2048; idx += 256) {
        int k = idx >> 5;
        int c4 = idx & 31;
        float4 v = (c4 < 16) ? ((const float4*)(W_mu + (size_t)k * HD))[c4]
                             : ((const float4*)(W_sig + (size_t)k * HD))[c4 - 16];
        __half2 h0 = __floats2half2_rn(v.x, v.y);
        __half2 h1 = __floats2half2_rn(v.z, v.w);
        uint2 pk; pk.x = *(unsigned*)&h0; pk.y = *(unsigned*)&h1;
        *(uint2*)&Bs[k * 136 + c4 * 4] = pk;
    }
    __syncthreads();

    int rg = w >> 1;
    int ch = (w & 1) * 4;
    wmma::fragment<wmma::accumulator, 16, 16, 16, float> c[4];
#pragma unroll
    for (int f = 0; f < 4; f++) wmma::fill_fragment(c[f], 0.0f);
#pragma unroll
    for (int k = 0; k < 4; k++) {
        wmma::fragment<wmma::matrix_a, 16, 16, 16, __half, wmma::row_major> a;
        wmma::load_matrix_sync(a, &As[rg * 16 * 72 + k * 16], 72);
#pragma unroll
        for (int f = 0; f < 4; f++) {
            wmma::fragment<wmma::matrix_b, 16, 16, 16, __half, wmma::row_major> b;
            wmma::load_matrix_sync(b, &Bs[k * 16 * 136 + (ch + f) * 16], 136);
            wmma::mma_sync(c[f], a, b, c[f]);
        }
    }
    __syncthreads();
#pragma unroll
    for (int f = 0; f < 4; f++)
        wmma::store_matrix_sync(Cs + (rg * 16) * 132 + (ch + f) * 16, c[f], 132,
                                wmma::mem_row_major);
    __syncthreads();

    int tx = tid & 15, ty = tid >> 4;
    float4 bm = *(const float4*)(b_mu + tx * 4);
    float4 bsg = *(const float4*)(b_sig + tx * 4);
#pragma unroll
    for (int i = 0; i < 4; i++) {
        int r = ty * 4 + i;
        int row = r0 + r;
        if (row < N) {
            const float* pm = Cs + r * 132 + tx * 4;
            const float* ps = Cs + r * 132 + 64 + tx * 4;
            float4 nz = *(const float4*)(noise + (size_t)row * HD + tx * 4);
            float4 o;
            o.x = (pm[0] + bm.x) + nz.x * __expf(ps[0] + bsg.x);
            o.y = (pm[1] + bm.y) + nz.y * __expf(ps[1] + bsg.y);
            o.z = (pm[2] + bm.z) + nz.z * __expf(ps[2] + bsg.z);
            o.w = (pm[3] + bm.w) + nz.w * __expf(ps[3] + bsg.w);
            *(float4*)(out + (size_t)row * HD + tx * 4) = o;
        }
    }
}

// ---------------------------------------------------------------------------
// Tail zeroing: re-zero counters + ticket for the NEXT sequence run.
// ---------------------------------------------------------------------------
__global__ void zero_kernel() {
    int i = blockIdx.x * blockDim.x + threadIdx.x;
    const int n4 = (2 * NN + 32) / 4;
    if (i < n4) ((int4*)g_cnt)[i] = make_int4(0, 0, 0, 0);
}

// ---------------------------------------------------------------------------
// Launch — R14 structure; fill is now atomic-free
// ---------------------------------------------------------------------------
static cudaStream_t s2 = nullptr;
static cudaEvent_t  evScan = nullptr, evGemm = nullptr;

extern "C" void kernel_launch(void* const* d_in, const int* in_sizes, int n_in,
                              void* d_out, int out_size) {
    const float* feat  = (const float*)d_in[0];
    const int*   src   = (const int*)d_in[1];
    const int*   dst   = (const int*)d_in[2];
    const float* noise = (const float*)d_in[3];
    const float* W1    = (const float*)d_in[4];
    const float* b1    = (const float*)d_in[5];
    const float* W_mu  = (const float*)d_in[6];
    const float* b_mu  = (const float*)d_in[7];
    const float* W_sig = (const float*)d_in[8];
    const float* b_sig = (const float*)d_in[9];

    int N = in_sizes[0] / FD;
    int E = in_sizes[1];

    if (s2 == nullptr) {
        cudaStreamCreateWithFlags(&s2, cudaStreamNonBlocking);
        cudaEventCreateWithFlags(&evScan, cudaEventDisableTiming);
        cudaEventCreateWithFlags(&evGemm, cudaEventDisableTiming);
    }

    deg_kernel<<<(E / 4 + 255) / 256, 256>>>(src, dst, E);
    scan_norm_kernel<<<(N + 255) / 256, 256>>>(N);
    cudaEventRecord(evScan, 0);

    // gemm1 (needs nsrc only) overlaps with fill on stream 2
    cudaStreamWaitEvent(s2, evScan, 0);
    gemm1_kernel<<<(N + 63) / 64, 256, 0, s2>>>(feat, W1, N);
    cudaEventRecord(evGemm, s2);

    fill_kernel<<<(E + 255) / 256, 256>>>(src, dst, E);
    cudaStreamWaitEvent(0, evGemm, 0);

    int gblocks = ((N + 1) * 32 + 255) / 256;   // +1 warp zeroes y16 sentinel row
    gather1_kernel<<<gblocks, 256>>>(b1, N);
    gather2_kernel<<<gblocks, 256>>>(N);

    final_kernel<<<(N + 63) / 64, 256>>>(noise, W_mu, b_mu, W_sig, b_sig,
                                         (float*)d_out, N);

    // Re-zero counters for the next replay (tail, off the critical head)
    zero_kernel<<<((2 * NN + 32) / 4 + 255) / 256, 256>>>();
}

// round 16
// speedup vs baseline: 1.1110x; 1.0132x over previous
#include <cuda_runtime.h>
#include <cuda_fp16.h>
#include <mma.h>
#include <math.h>

using namespace nvcuda;

#define NN 100000
#define EE 1600000
#define FD 128
#define HD 64
#define CSR_CAP (EE + 7 * NN + 16)

// Scratch (device globals; zero at module load, re-zeroed by zero_kernel each run)
__device__ int    g_cnt[2 * NN + 32];       // [0..NN)=out, [NN..2NN)=in, [2NN]=scan ticket
__device__ float  g_nsrc[NN];
__device__ float  g_ndst[NN];
__device__ int    g_off[NN];
__device__ int    g_rank[EE];               // per-edge arrival rank within dst segment
__device__ int    g_csr[CSR_CAP];           // padded to mult-of-8 per node; sentinel = NN
__device__ __half g_x16[(size_t)(NN + 1) * HD];  // row NN = zero sentinel
__device__ __half g_y16[(size_t)(NN + 1) * HD];  // row NN = zero sentinel
__device__ __half g_a16[(size_t)NN * HD];

// ---------------------------------------------------------------------------
// Degrees + per-edge rank. 1 edge/thread: max resident-atomic MLP (the shape
// that won for fill in R4/R5; deg occ was 62.9% at 4/thread).
// ---------------------------------------------------------------------------
__global__ void deg_kernel(const int* __restrict__ src, const int* __restrict__ dst, int E) {
    int i = blockIdx.x * blockDim.x + threadIdx.x;
    if (i < E) {
        atomicAdd(&g_cnt[src[i]], 1);
        g_rank[i] = atomicAdd(&g_cnt[NN + dst[i]], 1);
    }
}

// ---------------------------------------------------------------------------
// Scan + norm fused; scans PADDED degrees (mult-of-8), writes sentinels
// ---------------------------------------------------------------------------
__global__ void __launch_bounds__(256) scan_norm_kernel(int N) {
    __shared__ int wsum[8];
    __shared__ int sbase;
    int i = blockIdx.x * 256 + threadIdx.x;
    int lane = threadIdx.x & 31, wid = threadIdx.x >> 5;

    int cin = (i < N) ? g_cnt[NN + i] : 0;
    int pad = (cin + 7) & ~7;
    int x = pad;
#pragma unroll
    for (int o = 1; o < 32; o <<= 1) {
        int n = __shfl_up_sync(0xffffffffu, x, o);
        if (lane >= o) x += n;
    }
    if (lane == 31) wsum[wid] = x;
    __syncthreads();
    if (threadIdx.x == 0) {
        int run = 0;
#pragma unroll
        for (int w = 0; w < 8; w++) { run += wsum[w]; wsum[w] = run; }
        sbase = atomicAdd(&g_cnt[2 * NN], run);
    }
    __syncthreads();
    int excl = x - pad + (wid > 0 ? wsum[wid - 1] : 0) + sbase;
    if (i < N) {
        g_off[i] = excl;
        g_nsrc[i] = rsqrtf(fmaxf((float)g_cnt[i], 1.0f));
        g_ndst[i] = rsqrtf(fmaxf((float)cin, 1.0f));
        for (int s = cin; s < pad; s++) g_csr[excl + s] = NN;   // zero-row sentinels
    }
}

// ---------------------------------------------------------------------------
// Fill CSR: ATOMIC-FREE — slot is off[dst] + precomputed rank (R15-proven).
// ---------------------------------------------------------------------------
__global__ void fill_kernel(const int* __restrict__ src, const int* __restrict__ dst, int E) {
    int i = blockIdx.x * blockDim.x + threadIdx.x;
    if (i < E) {
        int d = dst[i];
        g_csr[g_off[d] + g_rank[i]] = src[i];
    }
}

// ---------------------------------------------------------------------------
// GEMM1 (wmma HMMA, R9-proven): x16 = fp16( (feat * nsrc) @ W1 );
// also stores zeros into sentinel row N.
// ---------------------------------------------------------------------------
__global__ void __launch_bounds__(256) gemm1_kernel(const float* __restrict__ feat,
                                                    const float* __restrict__ W1, int N) {
    __shared__ __align__(32) __half As[64][136];
    __shared__ __align__(32) __half Bs[128][72];
    int tid = threadIdx.x;
    int w = tid >> 5;
    int r0 = blockIdx.x * 64;

    for (int idx = tid; idx < 2048; idx += 256) {
        int r = idx >> 5;
        int c4 = idx & 31;
        int row = r0 + r;
        float4 v = make_float4(0.f, 0.f, 0.f, 0.f);
        float s = 0.f;
        if (row < N) {
            v = ((const float4*)(feat + (size_t)row * FD))[c4];
            s = g_nsrc[row];
        }
        __half2 h0 = __floats2half2_rn(v.x * s, v.y * s);
        __half2 h1 = __floats2half2_rn(v.z * s, v.w * s);
        uint2 pk; pk.x = *(unsigned*)&h0; pk.y = *(unsigned*)&h1;
        *(uint2*)&As[r][c4 * 4] = pk;
    }
    for (int idx = tid; idx < 2048; idx += 256) {
        int k = idx >> 4;
        int c4 = idx & 15;
        float4 v = ((const float4*)(W1 + (size_t)k * HD))[c4];
        __half2 h0 = __floats2half2_rn(v.x, v.y);
        __half2 h1 = __floats2half2_rn(v.z, v.w);
        uint2 pk; pk.x = *(unsigned*)&h0; pk.y = *(unsigned*)&h1;
        *(uint2*)&Bs[k][c4 * 4] = pk;
    }
    __syncthreads();

    int rg = w >> 1;
    int cg = (w & 1) * 2;
    wmma::fragment<wmma::accumulator, 16, 16, 16, float> c0, c1;
    wmma::fill_fragment(c0, 0.0f);
    wmma::fill_fragment(c1, 0.0f);
#pragma unroll
    for (int k = 0; k < 8; k++) {
        wmma::fragment<wmma::matrix_a, 16, 16, 16, __half, wmma::row_major> a;
        wmma::fragment<wmma::matrix_b, 16, 16, 16, __half, wmma::row_major> b0, b1;
        wmma::load_matrix_sync(a, &As[rg * 16][k * 16], 136);
        wmma::load_matrix_sync(b0, &Bs[k * 16][cg * 16], 72);
        wmma::load_matrix_sync(b1, &Bs[k * 16][(cg + 1) * 16], 72);
        wmma::mma_sync(c0, a, b0, c0);
        wmma::mma_sync(c1, a, b1, c1);
    }
    __syncthreads();

    float* Cs = (float*)&As[0][0];
    wmma::store_matrix_sync(Cs + (rg * 16) * 68 + cg * 16, c0, 68, wmma::mem_row_major);
    wmma::store_matrix_sync(Cs + (rg * 16) * 68 + (cg + 1) * 16, c1, 68, wmma::mem_row_major);
    __syncthreads();

    for (int idx = tid; idx < 1024; idx += 256) {
        int r = idx >> 4;
        int c4 = idx & 15;
        int row = r0 + r;
        if (row <= N) {     // row N: acc==0 (guarded loads) -> writes zero sentinel row
            const float* p = Cs + r * 68 + c4 * 4;
            __half2 h0 = __floats2half2_rn(p[0], p[1]);
            __half2 h1 = __floats2half2_rn(p[2], p[3]);
            uint2 pk; pk.x = *(unsigned*)&h0; pk.y = *(unsigned*)&h1;
            *(uint2*)(g_x16 + (size_t)row * HD + c4 * 4) = pk;
        }
    }
}

// ---------------------------------------------------------------------------
// Shuffle-free gather, 8 edges/iter (R15-proven)
// ---------------------------------------------------------------------------
__device__ __forceinline__ void gather_row_fast(const __half* __restrict__ X,
                                                int beg, int end, int g, int sl,
                                                float acc[4]) {
#pragma unroll 2
    for (int j = beg; j < end; j += 8) {
        int4 rr = *(const int4*)&g_csr[j + 4 * g];   // warp-uniform per half
        uint2 q0 = *(const uint2*)(X + (size_t)rr.x * HD + sl * 4);
        uint2 q1 = *(const uint2*)(X + (size_t)rr.y * HD + sl * 4);
        uint2 q2 = *(const uint2*)(X + (size_t)rr.z * HD + sl * 4);
        uint2 q3 = *(const uint2*)(X + (size_t)rr.w * HD + sl * 4);
        float2 a0 = __half22float2(*(__half2*)&q0.x);
        float2 b0 = __half22float2(*(__half2*)&q0.y);
        float2 a1 = __half22float2(*(__half2*)&q1.x);
        float2 b1 = __half22float2(*(__half2*)&q1.y);
        float2 a2 = __half22float2(*(__half2*)&q2.x);
        float2 b2 = __half22float2(*(__half2*)&q2.y);
        float2 a3 = __half22float2(*(__half2*)&q3.x);
        float2 b3 = __half22float2(*(__half2*)&q3.y);
        acc[0] += (a0.x + a1.x) + (a2.x + a3.x);
        acc[1] += (a0.y + a1.y) + (a2.y + a3.y);
        acc[2] += (b0.x + b1.x) + (b2.x + b3.x);
        acc[3] += (b0.y + b1.y) + (b2.y + b3.y);
    }
#pragma unroll
    for (int k = 0; k < 4; k++)
        acc[k] += __shfl_xor_sync(0xffffffffu, acc[k], 16);
}

__global__ void __launch_bounds__(256) gather1_kernel(const float* __restrict__ b1, int N) {
    int warp = (blockIdx.x * blockDim.x + threadIdx.x) >> 5;
    int lane = threadIdx.x & 31;
    int g = lane >> 4, sl = lane & 15;
    if (warp > N) return;
    if (warp == N) {        // zero sentinel row of y16
        if (g == 0) *(uint2*)(g_y16 + (size_t)N * HD + sl * 4) = make_uint2(0u, 0u);
        return;
    }
    int beg = g_off[warp];
    int cin = g_cnt[NN + warp];
    int end = beg + ((cin + 7) & ~7);

    float acc[4] = {0.f, 0.f, 0.f, 0.f};
    gather_row_fast(g_x16, beg, end, g, sl, acc);

    float nd = g_ndst[warp];
    float ns = g_nsrc[warp];
    float4 b = *(const float4*)(b1 + sl * 4);
    float o0 = fmaxf(acc[0] * nd + b.x, 0.f) * ns;
    float o1 = fmaxf(acc[1] * nd + b.y, 0.f) * ns;
    float o2 = fmaxf(acc[2] * nd + b.z, 0.f) * ns;
    float o3 = fmaxf(acc[3] * nd + b.w, 0.f) * ns;
    if (g == 0) {
        __half2 h0 = __floats2half2_rn(o0, o1);
        __half2 h1 = __floats2half2_rn(o2, o3);
        uint2 pk; pk.x = *(unsigned*)&h0; pk.y = *(unsigned*)&h1;
        *(uint2*)(g_y16 + (size_t)warp * HD + sl * 4) = pk;
    }
}

__global__ void __launch_bounds__(256) gather2_kernel(int N) {
    int warp = (blockIdx.x * blockDim.x + threadIdx.x) >> 5;
    int lane = threadIdx.x & 31;
    int g = lane >> 4, sl = lane & 15;
    if (warp >= N) return;
    int beg = g_off[warp];
    int cin = g_cnt[NN + warp];
    int end = beg + ((cin + 7) & ~7);

    float acc[4] = {0.f, 0.f, 0.f, 0.f};
    gather_row_fast(g_y16, beg, end, g, sl, acc);

    float nd = g_ndst[warp];
    if (g == 0) {
        __half2 h0 = __floats2half2_rn(acc[0] * nd, acc[1] * nd);
        __half2 h1 = __floats2half2_rn(acc[2] * nd, acc[3] * nd);
        uint2 pk; pk.x = *(unsigned*)&h0; pk.y = *(unsigned*)&h1;
        *(uint2*)(g_a16 + (size_t)warp * HD + sl * 4) = pk;
    }
}

// ---------------------------------------------------------------------------
// Final (wmma HMMA dual-GEMM, R9-proven) with __expf epilogue
// ---------------------------------------------------------------------------
__global__ void __launch_bounds__(256) final_kernel(const float* __restrict__ noise,
                                                    const float* __restrict__ W_mu,
                                                    const float* __restrict__ b_mu,
                                                    const float* __restrict__ W_sig,
                                                    const float* __restrict__ b_sig,
                                                    float* __restrict__ out, int N) {
    __shared__ __align__(32) char sbuf[64 * 132 * 4];    // 33792 B union
    __half* As = (__half*)sbuf;                          // [64][72]  = 9216 B
    __half* Bs = (__half*)(sbuf + 9216);                 // [64][136] = 17408 B
    float*  Cs = (float*)sbuf;                           // [64][132] (after mma)
    int tid = threadIdx.x;
    int w = tid >> 5;
    int r0 = blockIdx.x * 64;

    for (int idx = tid; idx < 1024; idx += 256) {
        int r = idx >> 4;
        int c4 = idx & 15;
        int row = r0 + r;
        uint2 pk = make_uint2(0u, 0u);
        if (row < N) pk = *(const uint2*)(g_a16 + (size_t)row * HD + c4 * 4);
        *(uint2*)&As[r * 72 + c4 * 4] = pk;
    }
    for (int idx = tid; idx < 2048; idx += 256) {
        int k = idx >> 5;
        int c4 = idx & 31;
        float4 v = (c4 < 16) ? ((const float4*)(W_mu + (size_t)k * HD))[c4]
                             : ((const float4*)(W_sig + (size_t)k * HD))[c4 - 16];
        __half2 h0 = __floats2half2_rn(v.x, v.y);
        __half2 h1 = __floats2half2_rn(v.z, v.w);
        uint2 pk; pk.x = *(unsigned*)&h0; pk.y = *(unsigned*)&h1;
        *(uint2*)&Bs[k * 136 + c4 * 4] = pk;
    }
    __syncthreads();

    int rg = w >> 1;
    int ch = (w & 1) * 4;
    wmma::fragment<wmma::accumulator, 16, 16, 16, float> c[4];
#pragma unroll
    for (int f = 0; f < 4; f++) wmma::fill_fragment(c[f], 0.0f);
#pragma unroll
    for (int k = 0; k < 4; k++) {
        wmma::fragment<wmma::matrix_a, 16, 16, 16, __half, wmma::row_major> a;
        wmma::load_matrix_sync(a, &As[rg * 16 * 72 + k * 16], 72);
#pragma unroll
        for (int f = 0; f < 4; f++) {
            wmma::fragment<wmma::matrix_b, 16, 16, 16, __half, wmma::row_major> b;
            wmma::load_matrix_sync(b, &Bs[k * 16 * 136 + (ch + f) * 16], 136);
            wmma::mma_sync(c[f], a, b, c[f]);
        }
    }
    __syncthreads();
#pragma unroll
    for (int f = 0; f < 4; f++)
        wmma::store_matrix_sync(Cs + (rg * 16) * 132 + (ch + f) * 16, c[f], 132,
                                wmma::mem_row_major);
    __syncthreads();

    int tx = tid & 15, ty = tid >> 4;
    float4 bm = *(const float4*)(b_mu + tx * 4);
    float4 bsg = *(const float4*)(b_sig + tx * 4);
#pragma unroll
    for (int i = 0; i < 4; i++) {
        int r = ty * 4 + i;
        int row = r0 + r;
        if (row < N) {
            const float* pm = Cs + r * 132 + tx * 4;
            const float* ps = Cs + r * 132 + 64 + tx * 4;
            float4 nz = *(const float4*)(noise + (size_t)row * HD + tx * 4);
            float4 o;
            o.x = (pm[0] + bm.x) + nz.x * __expf(ps[0] + bsg.x);
            o.y = (pm[1] + bm.y) + nz.y * __expf(ps[1] + bsg.y);
            o.z = (pm[2] + bm.z) + nz.z * __expf(ps[2] + bsg.z);
            o.w = (pm[3] + bm.w) + nz.w * __expf(ps[3] + bsg.w);
            *(float4*)(out + (size_t)row * HD + tx * 4) = o;
        }
    }
}

// ---------------------------------------------------------------------------
// Zeroing: re-zero counters + ticket for the NEXT sequence run.
// Runs on s2 concurrently with final (g_cnt last read by gather2).
// ---------------------------------------------------------------------------
__global__ void zero_kernel() {
    int i = blockIdx.x * blockDim.x + threadIdx.x;
    const int n4 = (2 * NN + 32) / 4;
    if (i < n4) ((int4*)g_cnt)[i] = make_int4(0, 0, 0, 0);
}

// ---------------------------------------------------------------------------
// Launch
// ---------------------------------------------------------------------------
static cudaStream_t s2 = nullptr;
static cudaEvent_t  evScan = nullptr, evGemm = nullptr, evG2 = nullptr, evZero = nullptr;

extern "C" void kernel_launch(void* const* d_in, const int* in_sizes, int n_in,
                              void* d_out, int out_size) {
    const float* feat  = (const float*)d_in[0];
    const int*   src   = (const int*)d_in[1];
    const int*   dst   = (const int*)d_in[2];
    const float* noise = (const float*)d_in[3];
    const float* W1    = (const float*)d_in[4];
    const float* b1    = (const float*)d_in[5];
    const float* W_mu  = (const float*)d_in[6];
    const float* b_mu  = (const float*)d_in[7];
    const float* W_sig = (const float*)d_in[8];
    const float* b_sig = (const float*)d_in[9];

    int N = in_sizes[0] / FD;
    int E = in_sizes[1];

    if (s2 == nullptr) {
        cudaStreamCreateWithFlags(&s2, cudaStreamNonBlocking);
        cudaEventCreateWithFlags(&evScan, cudaEventDisableTiming);
        cudaEventCreateWithFlags(&evGemm, cudaEventDisableTiming);
        cudaEventCreateWithFlags(&evG2,   cudaEventDisableTiming);
        cudaEventCreateWithFlags(&evZero, cudaEventDisableTiming);
    }

    deg_kernel<<<(E + 255) / 256, 256>>>(src, dst, E);
    scan_norm_kernel<<<(N + 255) / 256, 256>>>(N);
    cudaEventRecord(evScan, 0);

    // gemm1 (needs nsrc only) overlaps with fill on stream 2
    cudaStreamWaitEvent(s2, evScan, 0);
    gemm1_kernel<<<(N + 63) / 64, 256, 0, s2>>>(feat, W1, N);
    cudaEventRecord(evGemm, s2);

    fill_kernel<<<(E + 255) / 256, 256>>>(src, dst, E);
    cudaStreamWaitEvent(0, evGemm, 0);

    int gblocks = ((N + 1) * 32 + 255) / 256;   // +1 warp zeroes y16 sentinel row
    gather1_kernel<<<gblocks, 256>>>(b1, N);
    gather2_kernel<<<gblocks, 256>>>(N);
    cudaEventRecord(evG2, 0);

    // zero (next-run counters) on s2, concurrent with final
    cudaStreamWaitEvent(s2, evG2, 0);
    zero_kernel<<<((2 * NN + 32) / 4 + 255) / 256, 256, 0, s2>>>();
    cudaEventRecord(evZero, s2);

    final_kernel<<<(N + 63) / 64, 256>>>(noise, W_mu, b_mu, W_sig, b_sig,
                                         (float*)d_out, N);
    cudaStreamWaitEvent(0, evZero, 0);   // join so the graph's end waits on zero
}